// round 5
// baseline (speedup 1.0000x reference)
#include <cuda_runtime.h>
#include <math_constants.h>

// Shapes: img (B=2, C=1, D=192, H=192, W=192) float32.
static constexpr int B   = 2;
static constexpr int DD  = 192;
static constexpr int HH  = 192;
static constexpr int WW  = 192;
static constexpr int PLANE = HH * WW;        // 36864
static constexpr int VOL   = DD * PLANE;     // 7077888
static constexpr int NTOT  = B * VOL;        // 14155776

static constexpr int TX = 32;
static constexpr int TY = 16;
static constexpr int NTHR = TX * TY;         // 512
static constexpr int ZCHUNK = DD / 2;        // 96

// Ping-pong erosion buffers (scratch: __device__ globals, no allocation).
__device__ float g_buf0[NTOT];
__device__ float g_buf1[NTOT];

__global__ void zero_kernel(float* __restrict__ p, int n) {
    int i = blockIdx.x * blockDim.x + threadIdx.x;
    int stride = gridDim.x * blockDim.x;
    for (; i < n; i += stride) p[i] = 0.0f;
}

// One fused soft-skeletonize step:
//   Eout = soft_erode(A)                         (7-pt cross min, +inf pad)
//   d    = dilate3x3x3(Eout)                     (-inf pad)
//   delta = relu(A - d)
//   skel  = skel + relu(delta - skel*delta)
__global__ __launch_bounds__(NTHR)
void fused_step(const float* __restrict__ A,
                float* __restrict__ Eout,
                float* __restrict__ skel)
{
    // A ring: 4 planes of the input with halo 2 in x,y.
    __shared__ float As[4][TY + 4][TX + 4];
    // Erode plane scratch (halo 1 in x,y), rebuilt each z.
    __shared__ float eb[TY + 2][TX + 2];
    // Row-max of erode plane: rx[j%3][y][x] = max3x(e(j)), halo 1 in y.
    __shared__ float rxs[3][TY + 2][TX];

    const int tx  = threadIdx.x;
    const int ty  = threadIdx.y;
    const int tid = ty * TX + tx;
    const int x0  = blockIdx.x * TX;
    const int y0  = blockIdx.y * TY;
    const int bz  = blockIdx.z;
    const int b   = bz >> 1;
    const int z0  = (bz & 1) * ZCHUNK;
    const int z1  = z0 + ZCHUNK;

    const float* __restrict__ Ab = A    + b * VOL;
    float* __restrict__ Eb       = Eout + b * VOL;
    float* __restrict__ Sb       = skel + b * VOL;

    const float PINF = CUDART_INF_F;
    const float NINF = -CUDART_INF_F;

    // --- helpers -----------------------------------------------------------

    // Load input plane j into A-ring slot (j&3). z-OOB -> +inf plane;
    // xy-OOB positions -> +inf (erode min-padding).
    auto loadA = [&](int j) {
        float* s = &As[(j + 8) & 3][0][0];
        constexpr int NA = (TY + 4) * (TX + 4);   // 720
        if ((unsigned)j < (unsigned)DD) {
            const float* src = Ab + j * PLANE;
            for (int i = tid; i < NA; i += NTHR) {
                int yy = i / (TX + 4);
                int xx = i - yy * (TX + 4);
                int gy = y0 + yy - 2;
                int gx = x0 + xx - 2;
                float v = PINF;
                if ((unsigned)gy < (unsigned)HH && (unsigned)gx < (unsigned)WW)
                    v = __ldg(src + gy * WW + gx);
                s[i] = v;
            }
        } else {
            for (int i = tid; i < NA; i += NTHR) s[i] = PINF;
        }
    };

    // Compute erode plane j into eb (halo 1). Invalid (z or xy OOB) -> -inf
    // so the downstream dilate-max ignores it.
    auto compute_e = [&](int j) {
        const int sj  = (j + 8) & 3;
        const int sjm = (j + 7) & 3;
        const int sjp = (j + 9) & 3;
        const bool jv = (unsigned)j < (unsigned)DD;
        constexpr int NE = (TY + 2) * (TX + 2);   // 612
        for (int i = tid; i < NE; i += NTHR) {
            int yy = i / (TX + 2);
            int xx = i - yy * (TX + 2);
            int gy = y0 + yy - 1;
            int gx = x0 + xx - 1;
            float r = NINF;
            if (jv && (unsigned)gy < (unsigned)HH && (unsigned)gx < (unsigned)WW) {
                float m = As[sj][yy + 1][xx + 1];
                m = fminf(m, As[sjm][yy + 1][xx + 1]);
                m = fminf(m, As[sjp][yy + 1][xx + 1]);
                m = fminf(m, As[sj][yy    ][xx + 1]);
                m = fminf(m, As[sj][yy + 2][xx + 1]);
                m = fminf(m, As[sj][yy + 1][xx    ]);
                m = fminf(m, As[sj][yy + 1][xx + 2]);
                r = m;
            }
            eb[yy][xx] = r;
        }
    };

    // rx(j) = max3x(e(j)) into rx-ring slot ((j+3)%3); optionally store the
    // interior of e(j) to gmem (each plane written by exactly one chunk).
    auto compute_rx_store = [&](int j, bool do_store) {
        const int sr = (j + 3) % 3;               // j >= -1
        constexpr int NR = (TY + 2) * TX;         // 576
        for (int i = tid; i < NR; i += NTHR) {
            int yy = i >> 5;                       // TX == 32
            int x  = i & 31;
            float m = fmaxf(fmaxf(eb[yy][x], eb[yy][x + 1]), eb[yy][x + 2]);
            rxs[sr][yy][x] = m;
        }
        if (do_store) {
            Eb[j * PLANE + (y0 + ty) * WW + (x0 + tx)] = eb[ty + 1][tx + 1];
        }
    };

    // Output at plane z: dilate from rx ring, delta, skel update.
    auto do_output = [&](int z) {
        const int s0 = (z + 2) % 3;  // rx(z-1)
        const int s1 = (z + 3) % 3;  // rx(z)
        const int s2 = (z + 4) % 3;  // rx(z+1)
        float m = NINF;
        #pragma unroll
        for (int dy = 0; dy < 3; dy++) {
            m = fmaxf(m, rxs[s0][ty + dy][tx]);
            m = fmaxf(m, rxs[s1][ty + dy][tx]);
            m = fmaxf(m, rxs[s2][ty + dy][tx]);
        }
        float a = As[(z + 8) & 3][ty + 2][tx + 2];
        float delta = fmaxf(a - m, 0.0f);
        int g = z * PLANE + (y0 + ty) * WW + (x0 + tx);
        float s = Sb[g];
        s = s + fmaxf(delta - s * delta, 0.0f);
        Sb[g] = s;
    };

    // --- prologue: prime A ring (z0-2..z0+1), e/rx planes z0-1 and z0 ------
    loadA(z0 - 2);
    loadA(z0 - 1);
    loadA(z0);
    loadA(z0 + 1);
    __syncthreads();

    compute_e(z0 - 1);
    __syncthreads();
    compute_rx_store(z0 - 1, false);
    __syncthreads();

    compute_e(z0);
    loadA(z0 + 2);          // overwrites A(z0-2) slot (done being read)
    __syncthreads();
    compute_rx_store(z0, true);
    __syncthreads();

    // --- main z loop -------------------------------------------------------
    for (int z = z0; z < z1; z++) {
        __syncthreads();                 // protect eb / rx-slot / A-slot reuse
        compute_e(z + 1);                // reads A(z..z+2)
        loadA(z + 3);                    // writes slot (z+3)&3 == old A(z-1)
        __syncthreads();
        compute_rx_store(z + 1, (z + 1) < z1);
        __syncthreads();
        do_output(z);                    // reads rx(z-1..z+1), A(z) center
    }
}

extern "C" void kernel_launch(void* const* d_in, const int* in_sizes, int n_in,
                              void* d_out, int out_size) {
    const float* img = (const float*)d_in[0];
    float* skel = (float*)d_out;

    float *b0 = nullptr, *b1 = nullptr;
    cudaGetSymbolAddress((void**)&b0, g_buf0);
    cudaGetSymbolAddress((void**)&b1, g_buf1);

    // skel starts at 0: with the uniform update rule, step 0 yields exactly
    // relu(img - soft_open(img)).
    zero_kernel<<<2048, 256>>>(skel, NTOT);

    dim3 grid(WW / TX, HH / TY, 2 * B);   // 6 x 12 x 4 = 288 blocks
    dim3 blk(TX, TY, 1);                  // 512 threads

    const float* src = img;
    for (int k = 0; k <= 40; k++) {       // 41 fused steps: E_k -> E_{k+1}
        float* dst = (k & 1) ? b1 : b0;
        fused_step<<<grid, blk>>>(src, dst, skel);
        src = dst;
    }
}

// round 6
// speedup vs baseline: 1.4250x; 1.4250x over previous
#include <cuda_runtime.h>
#include <math_constants.h>

// Shapes: img (B=2, C=1, D=192, H=192, W=192) float32.
static constexpr int B   = 2;
static constexpr int DD  = 192;
static constexpr int HH  = 192;
static constexpr int WW  = 192;
static constexpr int PLANE = HH * WW;        // 36864
static constexpr int VOL   = DD * PLANE;     // 7077888
static constexpr int NTOT  = B * VOL;        // 14155776

static constexpr int TX   = 32;              // tile x
static constexpr int TY   = 32;              // tile y (2 rows per thread)
static constexpr int TYB  = 16;              // block y threads
static constexpr int NTHR = TX * TYB;        // 512
static constexpr int ZCHUNK = 24;
static constexpr int NCH    = DD / ZCHUNK;   // 8

// Ping-pong erosion buffers (scratch: __device__ globals, no allocation).
__device__ float g_buf0[NTOT];
__device__ float g_buf1[NTOT];

// One fused soft-skeletonize step:
//   Eout = soft_erode(A)                 (7-pt cross min, +inf pad)
//   d    = dilate3x3x3(Eout)             (-inf pad)
//   delta = relu(A - d)
//   skel  = first ? delta : skel + relu(delta - skel*delta)
__global__ __launch_bounds__(NTHR)
void fused_step(const float* __restrict__ A,
                float* __restrict__ Eout,
                float* __restrict__ skel,
                int first)
{
    // A ring: 4 planes of the input with halo 2 in x,y.
    __shared__ float As[4][TY + 4][TX + 4];      // 4*36*36*4 = 20736 B
    // Erode plane scratch (halo 1), rebuilt each z.
    __shared__ float eb[TY + 2][TX + 2];         // 34*34*4   =  4624 B
    // Row-max of erode plane: rxs[j%3][y][x] = max3x(e(j)), halo 1 in y.
    __shared__ float rxs[3][TY + 2][TX];         // 3*34*32*4 = 13056 B

    const int tx  = threadIdx.x;
    const int ty  = threadIdx.y;                 // 0..15
    const int tid = ty * TX + tx;
    const int x0  = blockIdx.x * TX;
    const int y0  = blockIdx.y * TY;
    const int bz  = blockIdx.z;
    const int b   = bz >> 3;                     // NCH == 8
    const int z0  = (bz & 7) * ZCHUNK;
    const int z1  = z0 + ZCHUNK;

    const float* __restrict__ Ab = A    + b * VOL;
    float* __restrict__ Eb       = Eout + b * VOL;
    float* __restrict__ Sb       = skel + b * VOL;

    const float PINF = CUDART_INF_F;
    const float NINF = -CUDART_INF_F;

    // Load input plane j into A-ring slot (j&3). z-OOB -> +inf plane;
    // xy-OOB positions -> +inf (erode min-padding).
    auto loadA = [&](int j) {
        float* s = &As[(j + 8) & 3][0][0];
        constexpr int NA = (TY + 4) * (TX + 4);   // 1296
        if ((unsigned)j < (unsigned)DD) {
            const float* src = Ab + j * PLANE;
            #pragma unroll
            for (int i = tid; i < NA; i += NTHR) {
                int yy = i / (TX + 4);
                int xx = i - yy * (TX + 4);
                int gy = y0 + yy - 2;
                int gx = x0 + xx - 2;
                float v = PINF;
                if ((unsigned)gy < (unsigned)HH && (unsigned)gx < (unsigned)WW)
                    v = __ldg(src + gy * WW + gx);
                s[i] = v;
            }
        } else {
            #pragma unroll
            for (int i = tid; i < NA; i += NTHR) s[i] = PINF;
        }
    };

    // Compute erode plane j into eb (halo 1). Invalid -> -inf so the
    // downstream dilate-max ignores it.
    auto compute_e = [&](int j) {
        const int sj  = (j + 8) & 3;
        const int sjm = (j + 7) & 3;
        const int sjp = (j + 9) & 3;
        const bool jv = (unsigned)j < (unsigned)DD;
        constexpr int NE = (TY + 2) * (TX + 2);   // 1156
        #pragma unroll
        for (int i = tid; i < NE; i += NTHR) {
            int yy = i / (TX + 2);
            int xx = i - yy * (TX + 2);
            int gy = y0 + yy - 1;
            int gx = x0 + xx - 1;
            float r = NINF;
            if (jv && (unsigned)gy < (unsigned)HH && (unsigned)gx < (unsigned)WW) {
                float m = As[sj][yy + 1][xx + 1];
                m = fminf(m, As[sjm][yy + 1][xx + 1]);
                m = fminf(m, As[sjp][yy + 1][xx + 1]);
                m = fminf(m, As[sj][yy    ][xx + 1]);
                m = fminf(m, As[sj][yy + 2][xx + 1]);
                m = fminf(m, As[sj][yy + 1][xx    ]);
                m = fminf(m, As[sj][yy + 1][xx + 2]);
                r = m;
            }
            eb[yy][xx] = r;
        }
    };

    // rx(j) = max3x(e(j)) into rx-ring slot ((j+3)%3); optionally store the
    // interior of e(j) to gmem (each plane written by exactly one chunk).
    auto compute_rx_store = [&](int j, bool do_store) {
        const int sr = (j + 3) % 3;               // j >= -1
        constexpr int NR = (TY + 2) * TX;         // 1088
        #pragma unroll
        for (int i = tid; i < NR; i += NTHR) {
            int yy = i >> 5;                       // TX == 32
            int x  = i & 31;
            float m = fmaxf(fmaxf(eb[yy][x], eb[yy][x + 1]), eb[yy][x + 2]);
            rxs[sr][yy][x] = m;
        }
        if (do_store) {
            float* dst = Eb + j * PLANE + (y0 + ty) * WW + (x0 + tx);
            dst[0]             = eb[ty + 1][tx + 1];
            dst[TYB * WW]      = eb[ty + TYB + 1][tx + 1];
        }
    };

    // Output at plane z: dilate from rx ring, delta, skel update. 2 rows.
    auto do_output = [&](int z) {
        const int s0 = (z + 2) % 3;  // rx(z-1)
        const int s1 = (z + 3) % 3;  // rx(z)
        const int s2 = (z + 4) % 3;  // rx(z+1)
        const int sa = (z + 8) & 3;
        #pragma unroll
        for (int h = 0; h < 2; h++) {
            const int yy = ty + h * TYB;
            float m = NINF;
            #pragma unroll
            for (int dy = 0; dy < 3; dy++) {
                m = fmaxf(m, rxs[s0][yy + dy][tx]);
                m = fmaxf(m, rxs[s1][yy + dy][tx]);
                m = fmaxf(m, rxs[s2][yy + dy][tx]);
            }
            float a = As[sa][yy + 2][tx + 2];
            float delta = fmaxf(a - m, 0.0f);
            int g = z * PLANE + (y0 + yy) * WW + (x0 + tx);
            if (first) {
                Sb[g] = delta;
            } else {
                float s = Sb[g];
                Sb[g] = s + fmaxf(delta - s * delta, 0.0f);
            }
        }
    };

    // --- prologue: prime A ring (z0-2..z0+1), e/rx planes z0-1 and z0 ------
    loadA(z0 - 2);
    loadA(z0 - 1);
    loadA(z0);
    loadA(z0 + 1);
    __syncthreads();

    compute_e(z0 - 1);
    __syncthreads();
    compute_rx_store(z0 - 1, false);
    __syncthreads();

    compute_e(z0);
    loadA(z0 + 2);          // overwrites A(z0-2) slot (done being read)
    __syncthreads();
    compute_rx_store(z0, true);
    __syncthreads();

    // --- main z loop -------------------------------------------------------
    for (int z = z0; z < z1; z++) {
        __syncthreads();                 // protect eb / rx-slot / A-slot reuse
        compute_e(z + 1);                // reads A(z..z+2)
        loadA(z + 3);                    // writes slot (z+3)&3 == old A(z-1)
        __syncthreads();
        compute_rx_store(z + 1, (z + 1) < z1);
        __syncthreads();
        do_output(z);                    // reads rx(z-1..z+1), A(z) center
    }
}

extern "C" void kernel_launch(void* const* d_in, const int* in_sizes, int n_in,
                              void* d_out, int out_size) {
    const float* img = (const float*)d_in[0];
    float* skel = (float*)d_out;

    float *b0 = nullptr, *b1 = nullptr;
    cudaGetSymbolAddress((void**)&b0, g_buf0);
    cudaGetSymbolAddress((void**)&b1, g_buf1);

    dim3 grid(WW / TX, HH / TY, NCH * B);   // 6 x 6 x 16 = 576 blocks
    dim3 blk(TX, TYB, 1);                   // 512 threads

    const float* src = img;
    for (int k = 0; k <= 40; k++) {         // 41 fused steps: E_k -> E_{k+1}
        float* dst = (k & 1) ? b1 : b0;
        fused_step<<<grid, blk>>>(src, dst, skel, k == 0 ? 1 : 0);
        src = dst;
    }
}